// round 16
// baseline (speedup 1.0000x reference)
#include <cuda_runtime.h>
#include <cuda_fp16.h>
#include <cstdint>

// ============================================================================
// IndRNN on GB300 — single kernel, zero scratch, BARRIER-FREE mainloop:
//   Prologue per CTA: W n-block fp32 (L2-hot) -> resident fp16 B in smem
//   (ROWB=80 padded, staged transpose).
//   Mainloop: A fragments loaded DIRECTLY from gmem fp32 (sector-perfect
//   float2 pattern) -> cvt fp16 -> registers; B via ldsm from resident smem.
//   No A smem stage, no cp.async, no __syncthreads in the chunk loop: warps
//   free-run through all 32 chunks.
//   Per 128-row tile: R8's half-tile dump+scan epilogue (3 syncs/tile).
// Shapes: B=64, T=512, D(K)=256, U(N)=512, M=B*T=32768
// rel_err ~ 2.35e-4 (identical fp16 roundings + MMA order to R5-R15).
// ============================================================================

#define U_DIM 512
#define K_DIM 256
#define T_DIM 512
#define MT 128
#define NT 128
#define ROWB 80                      // padded row stride, conflict-free ldmatrix
#define SUBT (128 * ROWB)            // 128x32 fp16 subtile: 10240 B
#define B_BASE 0                     // resident B: 8 subtiles = 81920 B
#define SC_BASE 81920                // scan buffer / prologue staging
#define SCROW 130
#define SCBYTES 33280                // 64 * 130 * 4
#define SMEM_BYTES (SC_BASE + SCBYTES)   // 115200 B -> occ 2

// ---------------------------------------------------------------- helpers
__device__ __forceinline__ uint32_t smem_u32(const void* p) {
    uint32_t a;
    asm("{ .reg .u64 t; cvta.to.shared.u64 t, %1; cvt.u32.u64 %0, t; }"
        : "=r"(a) : "l"(p));
    return a;
}
__device__ __forceinline__ void ldsm_x4(uint32_t* r, uint32_t addr) {
    asm volatile("ldmatrix.sync.aligned.m8n8.x4.shared.b16 {%0,%1,%2,%3}, [%4];"
                 : "=r"(r[0]), "=r"(r[1]), "=r"(r[2]), "=r"(r[3]) : "r"(addr));
}
__device__ __forceinline__ void mma_f16(float* c, const uint32_t* a,
                                        uint32_t b0, uint32_t b1) {
    asm volatile(
        "mma.sync.aligned.m16n8k16.row.col.f32.f16.f16.f32 "
        "{%0,%1,%2,%3}, {%4,%5,%6,%7}, {%8,%9}, {%0,%1,%2,%3};"
        : "+f"(c[0]), "+f"(c[1]), "+f"(c[2]), "+f"(c[3])
        : "r"(a[0]), "r"(a[1]), "r"(a[2]), "r"(a[3]), "r"(b0), "r"(b1));
}
__device__ __forceinline__ uint32_t pack_h2(__half a, __half b) {
    __half2 p(a, b);
    return *reinterpret_cast<uint32_t*>(&p);
}
__device__ __forceinline__ uint32_t cvt_h2(float2 v) {
    __half2 p = __floats2half2_rn(v.x, v.y);     // low = v.x (matches pack_h2)
    return *reinterpret_cast<uint32_t*>(&p);
}
__device__ __forceinline__ void sts8(uint32_t dst, uint32_t v0, uint32_t v1) {
    asm volatile("st.shared.v2.b32 [%0], {%1, %2};"
                 :: "r"(dst), "r"(v0), "r"(v1) : "memory");
}

// ---------------------------------------------------------------- kernel
// 256 threads = 8 warps in 4(m) x 2(n). Warp tile 32x64.
__global__ __launch_bounds__(256, 2)
void indrnn_df_kernel(const float* __restrict__ W,     // [K, N] fp32
                      const float* __restrict__ X,     // [M, K] fp32
                      const float* __restrict__ bias,  // [N]
                      const float* __restrict__ h0g,   // [B, U]
                      const float* __restrict__ ug,    // [U]
                      float* __restrict__ C)           // [M, U_DIM]
{
    extern __shared__ char smem[];
    const uint32_t sb = smem_u32(smem);
    float* const scf = reinterpret_cast<float*>(smem + SC_BASE);

    const int tid  = threadIdx.x;
    const int lane = tid & 31;
    const int wid  = tid >> 5;
    const int wm   = wid & 3;
    const int wn   = wid >> 2;
    const int n0   = blockIdx.x * NT;
    const int b    = blockIdx.y;
    const int mB   = b * T_DIM;

    // ========== prologue: resident B = W^T fp16 (staged transpose) ==========
    {
        float* stg = reinterpret_cast<float*>(smem + SC_BASE);  // 128x65 floats
        #pragma unroll 1
        for (int kb = 0; kb < 4; kb++) {
            const int k0 = kb * 64;
            #pragma unroll
            for (int i = 0; i < 32; i++) {
                int idx = i * 256 + tid;
                int r = idx >> 7, c = idx & 127;
                stg[c * 65 + r] = W[(size_t)(k0 + r) * U_DIM + n0 + c];
            }
            __syncthreads();
            const int n  = tid >> 1;
            const int hh = tid & 1;                 // k-half (subtile 2kb+hh)
            const uint32_t dst = sb + (uint32_t)(B_BASE + (2 * kb + hh) * SUBT
                                                 + n * ROWB);
            float v[32];
            #pragma unroll
            for (int j = 0; j < 32; j++)
                v[j] = stg[n * 65 + hh * 32 + j];
            #pragma unroll
            for (int q = 0; q < 8; q++)
                sts8(dst + q * 8,
                     pack_h2(__float2half_rn(v[q*4+0]), __float2half_rn(v[q*4+1])),
                     pack_h2(__float2half_rn(v[q*4+2]), __float2half_rn(v[q*4+3])));
            __syncthreads();
        }
    }

    // scan state: thread tid<128 owns column n0+tid
    float h = 0.0f, uc = 0.0f;
    if (tid < 128) {
        uc = fminf(fmaxf(ug[n0 + tid], 0.0f), 1.0f);
        h  = h0g[(size_t)b * U_DIM + n0 + tid];
    }

    // B ldsm lane offset (R8-proven, ROWB-padded)
    const uint32_t bOff = (uint32_t)(((lane & 7) + ((lane >> 4) & 1) * 8) * ROWB
                                     + ((lane >> 3) & 1) * 16);
    // A fragment gmem geometry
    const int aRowL = lane >> 2;                 // 0..7
    const int aColL = (lane & 3) * 2;            // 0,2,4,6
    // dump fragment coords
    const int colBase = wn * 64 + (lane & 3) * 2;
    const int rowBase = wm * 32 + (lane >> 2);

    #pragma unroll 1
    for (int tc = 0; tc < 4; tc++) {
        const int m0 = mB + tc * MT;

        float acc[2][8][4];
        #pragma unroll
        for (int mt = 0; mt < 2; mt++)
            #pragma unroll
            for (int nt = 0; nt < 8; nt++)
                #pragma unroll
                for (int q = 0; q < 4; q++)
                    acc[mt][nt][q] = 0.0f;

        const float* abase = X + (size_t)(m0 + wm * 32 + aRowL) * K_DIM + aColL;

        // -------- BARRIER-FREE chunk loop: 8 chunks of K=32 --------
        #pragma unroll 1
        for (int c = 0; c < 8; c++) {
            const float* ab = abase + c * 32;
            // load A fragments: 4 rows (+8 apart) x 4 col-groups (+8 apart)
            float2 a32[4][4];
            #pragma unroll
            for (int i = 0; i < 4; i++)
                #pragma unroll
                for (int j = 0; j < 4; j++)
                    a32[i][j] = *reinterpret_cast<const float2*>(
                        ab + (size_t)(i * 8) * K_DIM + j * 8);

            const uint32_t uB = sb + (uint32_t)(B_BASE + c * SUBT)
                                   + (uint32_t)(wn * 64 * ROWB) + bOff;
            #pragma unroll
            for (int ks = 0; ks < 2; ks++) {
                uint32_t ah[2][4];
                #pragma unroll
                for (int mt = 0; mt < 2; mt++) {
                    ah[mt][0] = cvt_h2(a32[2*mt    ][2*ks    ]);
                    ah[mt][1] = cvt_h2(a32[2*mt + 1][2*ks    ]);
                    ah[mt][2] = cvt_h2(a32[2*mt    ][2*ks + 1]);
                    ah[mt][3] = cvt_h2(a32[2*mt + 1][2*ks + 1]);
                }
                #pragma unroll
                for (int np = 0; np < 4; np++) {
                    uint32_t bh[4];
                    ldsm_x4(bh, uB + (uint32_t)(np * 16 * ROWB) + ks * 32);
                    #pragma unroll
                    for (int mt = 0; mt < 2; mt++) {
                        mma_f16(acc[mt][np * 2 + 0], ah[mt], bh[0], bh[1]);
                        mma_f16(acc[mt][np * 2 + 1], ah[mt], bh[2], bh[3]);
                    }
                }
            }
        }

        // ---- two half-tile dump+scan phases (rows p*64 .. p*64+63) ----
        #pragma unroll 1
        for (int p = 0; p < 2; p++) {
            __syncthreads();   // prev phase's scan reads done / mainloop done
            if ((wm >> 1) == p) {
                const int rloc = rowBase - p * 64;   // 0..63 for owning warps
                #pragma unroll
                for (int nt = 0; nt < 8; nt++) {
                    const int col = colBase + nt * 8;
                    float2 bv = *reinterpret_cast<const float2*>(bias + n0 + col);
                    #pragma unroll
                    for (int mt = 0; mt < 2; mt++) {
                        const int r = rloc + mt * 16;
                        float2 o0 = { acc[mt][nt][0] + bv.x, acc[mt][nt][1] + bv.y };
                        float2 o1 = { acc[mt][nt][2] + bv.x, acc[mt][nt][3] + bv.y };
                        *reinterpret_cast<float2*>(scf + (size_t)r * SCROW + col)       = o0;
                        *reinterpret_cast<float2*>(scf + (size_t)(r + 8) * SCROW + col) = o1;
                    }
                }
            }
            __syncthreads();
            if (tid < 128) {
                float* crow = C + (size_t)(m0 + p * 64) * U_DIM + n0 + tid;
                #pragma unroll
                for (int t = 0; t < 64; t += 8) {
                    float v[8];
                    #pragma unroll
                    for (int i = 0; i < 8; i++)
                        v[i] = scf[(size_t)(t + i) * SCROW + tid];
                    #pragma unroll
                    for (int i = 0; i < 8; i++) {
                        h = fmaxf(fmaf(h, uc, v[i]), 0.0f);
                        v[i] = h;
                    }
                    #pragma unroll
                    for (int i = 0; i < 8; i++)
                        crow[(size_t)(t + i) * U_DIM] = v[i];
                }
            }
        }
        __syncthreads();    // scan reads done before next tile's dump
    }
}

// ---------------------------------------------------------------- launch
extern "C" void kernel_launch(void* const* d_in, const int* in_sizes, int n_in,
                              void* d_out, int out_size)
{
    const float* x  = (const float*)d_in[0];  // [B,T,D]
    const float* h0 = (const float*)d_in[1];  // [B,U]
    const float* W  = (const float*)d_in[2];  // [D,U]
    const float* u  = (const float*)d_in[3];  // [U]
    const float* bb = (const float*)d_in[4];  // [U]
    float* out = (float*)d_out;               // [B,T,U]

    const int U = in_sizes[3];                // 512
    const int B = in_sizes[1] / U;            // 64

    cudaFuncSetAttribute(indrnn_df_kernel,
                         cudaFuncAttributeMaxDynamicSharedMemorySize, SMEM_BYTES);
    dim3 gg(U / NT, B);   // (4, 64) = 256 CTAs, single wave at occ 2
    indrnn_df_kernel<<<gg, 256, SMEM_BYTES>>>(W, x, bb, h0, u, out);
}

// round 17
// speedup vs baseline: 1.1064x; 1.1064x over previous
#include <cuda_runtime.h>
#include <cuda_fp16.h>
#include <cstdint>

// ============================================================================
// IndRNN on GB300 — ONE kernel: cooperative in-kernel prep + R8 fused core.
//   Phase 1 (per CTA): convert own x quarter (t-tile bx of batch by) fp32->fp16
//   into g_Xh; CTAs with by==0 also build g_Wt = W^T fp16 (staged transpose).
//   Sibling sync: per-batch flag (+4/replay) and W flag (+4/replay) with
//   monotonic epochs derived from atomicAdd returns (graph-replay safe; all
//   256 CTAs are wave-1 resident at occ 2; arrivals precede waits).
//   Phase 2: byte-identical R8 mainloop (KC=32, 3-stage cp.async ring,
//   32x64 warp tiles) + half-tile dump+scan epilogue.
// Shapes: B=64, T=512, D(K)=256, U(N)=512, M=B*T=32768
// rel_err ~ 2.35e-4 (identical fp16 roundings to R5-R16).
// ============================================================================

#define U_DIM 512
#define K_DIM 256
#define T_DIM 512
#define M_DIM 32768
#define MT 128
#define NT 128
#define KC 32
#define ROWB 80                        // 5*16: conflict-free ldmatrix
#define TSTG (128 * ROWB)              // one 128x32 fp16 tile: 10240 B
#define STG_B (2 * TSTG)               // A + B per stage: 20480 B
#define NSTAGE 3
#define STAGES_BYTES (NSTAGE * STG_B)  // 61440 B
#define SCROW 130
#define SCBYTES (64 * SCROW * 4)       // 33280 B (half tile)
#define SMEM_BYTES (STAGES_BYTES + SCBYTES)  // 94720 B -> occ 2

__device__ __half g_Wt[U_DIM * K_DIM];   // W^T [N][K] fp16
__device__ __half g_Xh[M_DIM * K_DIM];   // x   [M][K] fp16
__device__ unsigned g_cx[64];            // per-batch x-conversion flag (+4/replay)
__device__ unsigned g_cw;                // W-conversion flag (+4/replay)

// ---------------------------------------------------------------- helpers
__device__ __forceinline__ uint32_t smem_u32(const void* p) {
    uint32_t a;
    asm("{ .reg .u64 t; cvta.to.shared.u64 t, %1; cvt.u32.u64 %0, t; }"
        : "=r"(a) : "l"(p));
    return a;
}
__device__ __forceinline__ void ldsm_x4(uint32_t* r, uint32_t addr) {
    asm volatile("ldmatrix.sync.aligned.m8n8.x4.shared.b16 {%0,%1,%2,%3}, [%4];"
                 : "=r"(r[0]), "=r"(r[1]), "=r"(r[2]), "=r"(r[3]) : "r"(addr));
}
__device__ __forceinline__ void mma_f16(float* c, const uint32_t* a,
                                        uint32_t b0, uint32_t b1) {
    asm volatile(
        "mma.sync.aligned.m16n8k16.row.col.f32.f16.f16.f32 "
        "{%0,%1,%2,%3}, {%4,%5,%6,%7}, {%8,%9}, {%0,%1,%2,%3};"
        : "+f"(c[0]), "+f"(c[1]), "+f"(c[2]), "+f"(c[3])
        : "r"(a[0]), "r"(a[1]), "r"(a[2]), "r"(a[3]), "r"(b0), "r"(b1));
}
__device__ __forceinline__ void cp_async16(uint32_t dst, const void* src) {
    asm volatile("cp.async.cg.shared.global [%0], [%1], 16;"
                 :: "r"(dst), "l"(src) : "memory");
}
#define CP_COMMIT() asm volatile("cp.async.commit_group;" ::: "memory")
#define CP_WAIT1()  asm volatile("cp.async.wait_group 1;" ::: "memory")

__device__ __forceinline__ uint32_t pack_h2(__half a, __half b) {
    __half2 p(a, b);
    return *reinterpret_cast<uint32_t*>(&p);
}
__device__ __forceinline__ unsigned ld_acq(const unsigned* p) {
    unsigned v;
    asm volatile("ld.global.acquire.gpu.b32 %0, [%1];" : "=r"(v) : "l"(p));
    return v;
}

// ---------------------------------------------------------------- kernel
// 256 threads = 8 warps in 4(m) x 2(n). Warp tile 32x64.
__global__ __launch_bounds__(256, 2)
void indrnn_coop_kernel(const float* __restrict__ W,     // [K, N] fp32
                        const float* __restrict__ X,     // [M, K] fp32
                        const float* __restrict__ bias,  // [N]
                        const float* __restrict__ h0g,   // [B, U]
                        const float* __restrict__ ug,    // [U]
                        float* __restrict__ C)           // [M, U_DIM]
{
    extern __shared__ char smem[];
    const uint32_t sb = smem_u32(smem);
    float* const scf = reinterpret_cast<float*>(smem + STAGES_BYTES);

    const int tid  = threadIdx.x;
    const int lane = tid & 31;
    const int wid  = tid >> 5;
    const int wm   = wid & 3;
    const int wn   = wid >> 2;
    const int bx   = blockIdx.x;
    const int by   = blockIdx.y;
    const int n0   = bx * NT;
    const int mB   = by * T_DIM;

    // =================== phase 1: cooperative conversion ===================
    // x quarter: rows [mB + bx*128, +128) x K. 4096 uint4 outputs, 16/thread.
    {
        const size_t rbase = ((size_t)mB + (size_t)bx * 128) * K_DIM;
        const float4* xin = reinterpret_cast<const float4*>(X + rbase);
        uint4* xout = reinterpret_cast<uint4*>(g_Xh + rbase);
        #pragma unroll
        for (int i = 0; i < 16; i++) {
            int o = i * 256 + tid;              // uint4 index 0..4095
            float4 v0 = xin[o * 2];
            float4 v1 = xin[o * 2 + 1];
            uint4 r;
            r.x = pack_h2(__float2half_rn(v0.x), __float2half_rn(v0.y));
            r.y = pack_h2(__float2half_rn(v0.z), __float2half_rn(v0.w));
            r.z = pack_h2(__float2half_rn(v1.x), __float2half_rn(v1.y));
            r.w = pack_h2(__float2half_rn(v1.z), __float2half_rn(v1.w));
            xout[o] = r;
        }
    }
    // W^T block bx (n in [n0, n0+128), all K): only the 4 CTAs with by==0.
    if (by == 0) {
        float* stg = scf;   // staging: 128 x 65 floats (fits 33280 B)
        #pragma unroll 1
        for (int kb = 0; kb < 4; kb++) {
            const int k0 = kb * 64;
            #pragma unroll
            for (int i = 0; i < 32; i++) {
                int idx = i * 256 + tid;
                int r = idx >> 7, c = idx & 127;
                stg[c * 65 + r] = W[(size_t)(k0 + r) * U_DIM + n0 + c];
            }
            __syncthreads();
            const int n  = tid >> 1;
            const int hh = tid & 1;
            uint2* dst = reinterpret_cast<uint2*>(
                g_Wt + (size_t)(n0 + n) * K_DIM + k0 + hh * 32);
            #pragma unroll
            for (int q = 0; q < 4; q++) {
                float a0 = stg[n * 65 + hh * 32 + q * 8 + 0];
                float a1 = stg[n * 65 + hh * 32 + q * 8 + 1];
                float a2 = stg[n * 65 + hh * 32 + q * 8 + 2];
                float a3 = stg[n * 65 + hh * 32 + q * 8 + 3];
                float a4 = stg[n * 65 + hh * 32 + q * 8 + 4];
                float a5 = stg[n * 65 + hh * 32 + q * 8 + 5];
                float a6 = stg[n * 65 + hh * 32 + q * 8 + 6];
                float a7 = stg[n * 65 + hh * 32 + q * 8 + 7];
                uint2 o;
                o.x = pack_h2(__float2half_rn(a0), __float2half_rn(a1));
                o.y = pack_h2(__float2half_rn(a2), __float2half_rn(a3));
                dst[q * 2] = o;
                uint2 o2;
                o2.x = pack_h2(__float2half_rn(a4), __float2half_rn(a5));
                o2.y = pack_h2(__float2half_rn(a6), __float2half_rn(a7));
                dst[q * 2 + 1] = o2;
            }
            __syncthreads();
        }
    }
    // flags + waits (monotonic epochs; arrivals strictly before waits)
    __syncthreads();
    __threadfence();
    if (tid == 0) {
        unsigned r = atomicAdd(&g_cx[by], 1u);     // my arrival
        if (by == 0) atomicAdd(&g_cw, 1u);         // W arrival
        unsigned e = r >> 2;                       // replay epoch
        unsigned tgt = (e + 1u) * 4u;
        while (ld_acq(&g_cx[by]) < tgt) { }
        while (ld_acq(&g_cw) < tgt) { }
    }
    __syncthreads();

    // =================== phase 2: R8 fused mainloop + scan ===================
    float h = 0.0f, uc = 0.0f;
    if (tid < 128) {
        uc = fminf(fmaxf(ug[n0 + tid], 0.0f), 1.0f);
        h  = h0g[(size_t)by * U_DIM + n0 + tid];
    }

    const int cRow[2] = { (0*256 + tid) >> 2, (1*256 + tid) >> 2 };
    const int cC16 = tid & 3;
    const uint32_t aOff = (uint32_t)((lane & 15) * ROWB + (lane >> 4) * 16);
    const uint32_t bOff = (uint32_t)(((lane & 7) + ((lane >> 4) & 1) * 8) * ROWB
                                     + ((lane >> 3) & 1) * 16);
    const int colBase = wn * 64 + (lane & 3) * 2;
    const int rowBase = wm * 32 + (lane >> 2);

    auto issue_chunk = [&](int ch) {
        const uint32_t st = sb + (uint32_t)((ch % NSTAGE) * STG_B);
        const size_t mrow = (size_t)(mB + ((ch >> 3) << 7));
        const int kk = (ch & 7) * KC;
        #pragma unroll
        for (int i = 0; i < 2; i++) {
            cp_async16(st + (uint32_t)(cRow[i] * ROWB + cC16 * 16),
                       g_Xh + (mrow + cRow[i]) * K_DIM + kk + cC16 * 8);
            cp_async16(st + TSTG + (uint32_t)(cRow[i] * ROWB + cC16 * 16),
                       g_Wt + (size_t)(n0 + cRow[i]) * K_DIM + kk + cC16 * 8);
        }
        CP_COMMIT();
    };

    issue_chunk(0);
    issue_chunk(1);

    #pragma unroll 1
    for (int tc = 0; tc < T_DIM / MT; tc++) {
        const int m0 = mB + tc * MT;

        float acc[2][8][4];
        #pragma unroll
        for (int mt = 0; mt < 2; mt++)
            #pragma unroll
            for (int nt = 0; nt < 8; nt++)
                #pragma unroll
                for (int q = 0; q < 4; q++)
                    acc[mt][nt][q] = 0.0f;

        #pragma unroll 1
        for (int c = 0; c < 8; c++) {
            const int ch = tc * 8 + c;
            CP_WAIT1();
            __syncthreads();            // chunk ch resident; stage (ch+2)%3 free
            if (ch + 2 < 32) issue_chunk(ch + 2);

            const uint32_t uA = sb + (uint32_t)((ch % NSTAGE) * STG_B);
            const uint32_t uB = uA + TSTG;
            #pragma unroll
            for (int ks = 0; ks < 2; ks++) {
                const uint32_t kb = ks * 32;
                uint32_t ah[2][4];
                #pragma unroll
                for (int mt = 0; mt < 2; mt++)
                    ldsm_x4(ah[mt], uA + (uint32_t)((wm * 32 + mt * 16) * ROWB) + aOff + kb);
                #pragma unroll
                for (int np = 0; np < 4; np++) {
                    uint32_t bh[4];
                    ldsm_x4(bh, uB + (uint32_t)((wn * 64 + np * 16) * ROWB) + bOff + kb);
                    #pragma unroll
                    for (int mt = 0; mt < 2; mt++) {
                        mma_f16(acc[mt][np * 2 + 0], ah[mt], bh[0], bh[1]);
                        mma_f16(acc[mt][np * 2 + 1], ah[mt], bh[2], bh[3]);
                    }
                }
            }
        }

        // ---- two half-tile dump+scan phases (rows p*64 .. p*64+63) ----
        #pragma unroll 1
        for (int p = 0; p < 2; p++) {
            __syncthreads();   // prev phase's scan reads done
            if ((wm >> 1) == p) {
                const int rloc = rowBase - p * 64;   // 0..63 for owning warps
                #pragma unroll
                for (int nt = 0; nt < 8; nt++) {
                    const int col = colBase + nt * 8;
                    float2 bv = *reinterpret_cast<const float2*>(bias + n0 + col);
                    #pragma unroll
                    for (int mt = 0; mt < 2; mt++) {
                        const int r = rloc + mt * 16;
                        float2 o0 = { acc[mt][nt][0] + bv.x, acc[mt][nt][1] + bv.y };
                        float2 o1 = { acc[mt][nt][2] + bv.x, acc[mt][nt][3] + bv.y };
                        *reinterpret_cast<float2*>(scf + (size_t)r * SCROW + col)       = o0;
                        *reinterpret_cast<float2*>(scf + (size_t)(r + 8) * SCROW + col) = o1;
                    }
                }
            }
            __syncthreads();
            if (tid < 128) {
                float* crow = C + (size_t)(m0 + p * 64) * U_DIM + n0 + tid;
                #pragma unroll
                for (int t = 0; t < 64; t += 8) {
                    float v[8];
                    #pragma unroll
                    for (int i = 0; i < 8; i++)
                        v[i] = scf[(size_t)(t + i) * SCROW + tid];
                    #pragma unroll
                    for (int i = 0; i < 8; i++) {
                        h = fmaxf(fmaf(h, uc, v[i]), 0.0f);
                        v[i] = h;
                    }
                    #pragma unroll
                    for (int i = 0; i < 8; i++)
                        crow[(size_t)(t + i) * U_DIM] = v[i];
                }
            }
        }
        __syncthreads();    // scan reads done before next tile's dump
    }
}

// ---------------------------------------------------------------- launch
extern "C" void kernel_launch(void* const* d_in, const int* in_sizes, int n_in,
                              void* d_out, int out_size)
{
    const float* x  = (const float*)d_in[0];  // [B,T,D]
    const float* h0 = (const float*)d_in[1];  // [B,U]
    const float* W  = (const float*)d_in[2];  // [D,U]
    const float* u  = (const float*)d_in[3];  // [U]
    const float* bb = (const float*)d_in[4];  // [U]
    float* out = (float*)d_out;               // [B,T,U]

    const int U = in_sizes[3];                // 512
    const int B = in_sizes[1] / U;            // 64

    cudaFuncSetAttribute(indrnn_coop_kernel,
                         cudaFuncAttributeMaxDynamicSharedMemorySize, SMEM_BYTES);
    dim3 gg(U / NT, B);   // (4, 64) = 256 CTAs, all wave-1 resident at occ 2
    indrnn_coop_kernel<<<gg, 256, SMEM_BYTES>>>(W, x, bb, h0, u, out);
}